// round 1
// baseline (speedup 1.0000x reference)
#include <cuda_runtime.h>
#include <math.h>

// ---------------------------------------------------------------------------
// CDConv: offset-conv(3x3,128->256)+tanh -> depthwise(3x3) -> grid_sample ->
//         pointwise(1x1,128->256)
// Shapes: B=16, C=128, H=W=112, OUTC=256
// ---------------------------------------------------------------------------

#define BB   16
#define CC   128
#define HH   112
#define WW   112
#define HW   12544           // 112*112
#define MOFF 256             // 2*C  (offset conv output channels)
#define MOUT 256             // OUTC

// scratch (device globals; no runtime allocation allowed)
__device__ float g_offset[BB * MOFF * HW];   // [B, 2C, H, W]  ~205 MB
__device__ float g_dw[BB * CC * HW];         // depthwise out  ~103 MB
__device__ float g_samp[BB * CC * HW];       // sampled        ~103 MB

// ---------------------------------------------------------------------------
// Tiled SGEMM:  C[m,n] = sum_k A[m,k] * B[k,n]
//   M = 256 (template MM), N = B*HW = 200704, K template.
//   IM2COL=true : B[k,n] = im2col of x for 3x3 pad-1 conv (k -> cin,kh,kw)
//   IM2COL=false: B[k,n] = Bsrc[(b*K + k)*HW + rem]   (1x1 conv over sampled)
//   DO_TANH     : epilogue v = tanhf(acc + bias[m]); else v = acc
// Output layout: Cdst[((b*MM + m)*HW) + rem]
// BN=128 divides HW (12544 = 98*128) so each block sits in one image.
// ---------------------------------------------------------------------------

constexpr int BM = 128, BN = 128, BK = 8, TM = 8, TN = 8;

template <int K, int MM, bool IM2COL, bool DO_TANH>
__global__ __launch_bounds__(256)
void sgemm_conv(const float* __restrict__ A,
                const float* __restrict__ Bsrc,
                const float* __restrict__ bias,
                float* __restrict__ Cdst)
{
    __shared__ float As[BK][BM];
    __shared__ float Bs[BK][BN];

    const int tid  = threadIdx.x;
    const int tRow = tid >> 4;        // 0..15
    const int tCol = tid & 15;        // 0..15

    const int nBase   = blockIdx.x * BN;
    const int b_img   = nBase / HW;   // constant within block
    const int remBase = nBase % HW;
    const int mBase   = blockIdx.y * BM;

    // global-load thread mapping
    const int aRow = tid >> 1;              // 0..127
    const int aCol = (tid & 1) * 4;         // 0 or 4
    const int bRow = tid >> 5;              // 0..7
    const int bCol = (tid & 31) * 4;        // 0..124

    float acc[TM][TN];
#pragma unroll
    for (int i = 0; i < TM; i++)
#pragma unroll
        for (int j = 0; j < TN; j++) acc[i][j] = 0.f;

    float regM[TM], regN[TN];

    for (int k0 = 0; k0 < K; k0 += BK) {
        // ---- load A tile (transposed into As) ----
        float4 a4 = *reinterpret_cast<const float4*>(
            A + (mBase + aRow) * K + k0 + aCol);
        As[aCol + 0][aRow] = a4.x;
        As[aCol + 1][aRow] = a4.y;
        As[aCol + 2][aRow] = a4.z;
        As[aCol + 3][aRow] = a4.w;

        // ---- load B tile ----
        const int k = k0 + bRow;
        if (IM2COL) {
            const int cin = k / 9;
            const int r   = k - cin * 9;
            const int kh  = r / 3 - 1;
            const int kw  = r - (r / 3) * 3 - 1;
            const float* xp = Bsrc + (b_img * CC + cin) * HW;
#pragma unroll
            for (int i = 0; i < 4; i++) {
                const int rem = remBase + bCol + i;
                const int h   = rem / WW;
                const int w   = rem - h * WW;
                const int ih  = h + kh;
                const int iw  = w + kw;
                float v = 0.f;
                if ((unsigned)ih < (unsigned)HH && (unsigned)iw < (unsigned)WW)
                    v = __ldg(xp + ih * WW + iw);
                Bs[bRow][bCol + i] = v;
            }
        } else {
            const float4 b4 = *reinterpret_cast<const float4*>(
                Bsrc + (b_img * K + k) * HW + remBase + bCol);
            Bs[bRow][bCol + 0] = b4.x;
            Bs[bRow][bCol + 1] = b4.y;
            Bs[bRow][bCol + 2] = b4.z;
            Bs[bRow][bCol + 3] = b4.w;
        }
        __syncthreads();

        // ---- compute ----
#pragma unroll
        for (int kk = 0; kk < BK; kk++) {
#pragma unroll
            for (int i = 0; i < TM; i += 4) {
                float4 m4 = *reinterpret_cast<const float4*>(&As[kk][tRow * TM + i]);
                regM[i + 0] = m4.x; regM[i + 1] = m4.y;
                regM[i + 2] = m4.z; regM[i + 3] = m4.w;
            }
#pragma unroll
            for (int j = 0; j < TN; j += 4) {
                float4 n4 = *reinterpret_cast<const float4*>(&Bs[kk][tCol * TN + j]);
                regN[j + 0] = n4.x; regN[j + 1] = n4.y;
                regN[j + 2] = n4.z; regN[j + 3] = n4.w;
            }
#pragma unroll
            for (int i = 0; i < TM; i++)
#pragma unroll
                for (int j = 0; j < TN; j++)
                    acc[i][j] = fmaf(regM[i], regN[j], acc[i][j]);
        }
        __syncthreads();
    }

    // ---- epilogue ----
#pragma unroll
    for (int i = 0; i < TM; i++) {
        const int m = mBase + tRow * TM + i;
        float bi = 0.f;
        if (DO_TANH) bi = bias[m];
        float* cp = Cdst + (b_img * MM + m) * HW + remBase + tCol * TN;
        float out[TN];
#pragma unroll
        for (int j = 0; j < TN; j++) {
            float v = acc[i][j] + bi;
            if (DO_TANH) v = tanhf(v);
            out[j] = v;
        }
        *reinterpret_cast<float4*>(cp)     = make_float4(out[0], out[1], out[2], out[3]);
        *reinterpret_cast<float4*>(cp + 4) = make_float4(out[4], out[5], out[6], out[7]);
    }
}

// ---------------------------------------------------------------------------
// Depthwise 3x3, pad 1, groups=C, no bias.
// ---------------------------------------------------------------------------
__global__ __launch_bounds__(256)
void depthwise_k(const float* __restrict__ x,
                 const float* __restrict__ wgt,
                 float* __restrict__ out)
{
    const int idx = blockIdx.x * blockDim.x + threadIdx.x;
    if (idx >= BB * CC * HW) return;
    const int rem = idx % HW;
    const int bc  = idx / HW;
    const int c   = bc % CC;
    const int h   = rem / WW;
    const int w   = rem - h * WW;

    const float* wp = wgt + c * 9;
    const float* xp = x + bc * HW;

    float accv = 0.f;
#pragma unroll
    for (int kh = 0; kh < 3; kh++) {
        const int ih = h + kh - 1;
        if ((unsigned)ih >= (unsigned)HH) continue;
#pragma unroll
        for (int kw = 0; kw < 3; kw++) {
            const int iw = w + kw - 1;
            if ((unsigned)iw >= (unsigned)WW) continue;
            accv = fmaf(__ldg(xp + ih * WW + iw), __ldg(wp + kh * 3 + kw), accv);
        }
    }
    out[idx] = accv;
}

// ---------------------------------------------------------------------------
// Grid sample (bilinear, zeros padding, align_corners=False), with the
// reference's channel interleave:
//   x-coord for channel c = clip(base(2c)   + offset[b,2c  ,h,w], -1, 1)
//   y-coord for channel c = clip(base(2c+1) + offset[b,2c+1,h,w], -1, 1)
//   base(j) = gX(w) if j < C else gY(h)
// ---------------------------------------------------------------------------
__global__ __launch_bounds__(256)
void gridsample_k(const float* __restrict__ off,
                  const float* __restrict__ src,
                  float* __restrict__ dst)
{
    const int idx = blockIdx.x * blockDim.x + threadIdx.x;
    if (idx >= BB * CC * HW) return;
    const int rem = idx % HW;
    const int bc  = idx / HW;
    const int b   = bc / CC;
    const int c   = bc % CC;
    const int h   = rem / WW;
    const int w   = rem - h * WW;

    const float gx = -1.f + 2.f * (float)w / (float)(WW - 1);
    const float gy = -1.f + 2.f * (float)h / (float)(HH - 1);

    const int jx = 2 * c;
    const int jy = 2 * c + 1;
    const float basex = (jx < CC) ? gx : gy;
    const float basey = (jy < CC) ? gx : gy;

    const float offx = __ldg(off + (b * MOFF + jx) * HW + rem);
    const float offy = __ldg(off + (b * MOFF + jy) * HW + rem);

    float sx = fminf(fmaxf(basex + offx, -1.f), 1.f);
    float sy = fminf(fmaxf(basey + offy, -1.f), 1.f);

    // align_corners=False mapping
    const float ix = (sx + 1.f) * ((float)WW * 0.5f) - 0.5f;
    const float iy = (sy + 1.f) * ((float)HH * 0.5f) - 0.5f;

    const float x0f = floorf(ix);
    const float y0f = floorf(iy);
    const float wx  = ix - x0f;
    const float wy  = iy - y0f;
    const int x0 = (int)x0f;
    const int y0 = (int)y0f;

    const float* ch = src + bc * HW;

    auto gather = [&](int yi, int xi) -> float {
        if ((unsigned)yi < (unsigned)HH && (unsigned)xi < (unsigned)WW)
            return __ldg(ch + yi * WW + xi);
        return 0.f;
    };

    const float v00 = gather(y0,     x0);
    const float v01 = gather(y0,     x0 + 1);
    const float v10 = gather(y0 + 1, x0);
    const float v11 = gather(y0 + 1, x0 + 1);

    dst[idx] = v00 * (1.f - wx) * (1.f - wy)
             + v01 * wx         * (1.f - wy)
             + v10 * (1.f - wx) * wy
             + v11 * wx         * wy;
}

// ---------------------------------------------------------------------------
// launch
// ---------------------------------------------------------------------------
extern "C" void kernel_launch(void* const* d_in, const int* in_sizes, int n_in,
                              void* d_out, int out_size)
{
    const float* x        = (const float*)d_in[0];  // [16,128,112,112]
    const float* depth_w  = (const float*)d_in[1];  // [128,1,3,3]
    const float* point_w  = (const float*)d_in[2];  // [256,128,1,1]
    const float* offset_w = (const float*)d_in[3];  // [256,128,3,3]
    const float* offset_b = (const float*)d_in[4];  // [256]
    float* out = (float*)d_out;                     // [16,256,112,112]

    float* offset_p; cudaGetSymbolAddress((void**)&offset_p, g_offset);
    float* dw_p;     cudaGetSymbolAddress((void**)&dw_p,     g_dw);
    float* samp_p;   cudaGetSymbolAddress((void**)&samp_p,   g_samp);

    const int Ntot = BB * HW;                 // 200704
    dim3 gemmGrid(Ntot / BN, MOFF / BM);      // (1568, 2)

    // 1) offset = tanh(conv3x3(x, offset_w) + b)
    sgemm_conv<1152, MOFF, true, true><<<gemmGrid, 256>>>(
        offset_w, x, offset_b, offset_p);

    // 2) depthwise conv
    {
        const int total = BB * CC * HW;
        depthwise_k<<<(total + 255) / 256, 256>>>(x, depth_w, dw_p);
    }

    // 3) grid sample
    {
        const int total = BB * CC * HW;
        gridsample_k<<<(total + 255) / 256, 256>>>(offset_p, dw_p, samp_p);
    }

    // 4) pointwise 1x1 conv -> d_out
    sgemm_conv<128, MOUT, false, false><<<gemmGrid, 256>>>(
        point_w, samp_p, nullptr, out);
}